// round 1
// baseline (speedup 1.0000x reference)
#include <cuda_runtime.h>
#include <math.h>

#define S_DIM 2048
#define X_DIM 2048
#define F_DIM 3072
#define G_DIM 2
#define NSPLIT 8
#define XPS (X_DIM / NSPLIT)   // 256 x-columns per split

#define BM 128
#define BN 128
#define BK 16
#define SLD (BM + 4)           // padded smem leading dim (float4-align preserved)

// ---- scratch (no allocations allowed) ----
__device__ float g_w[G_DIM * F_DIM];              // precision 1/std^2
__device__ float g_const[G_DIM];                  // -0.5*F*log(2pi) - sum log std
__device__ float g_R[G_DIM * S_DIM];              // -0.5 * A[g,s]
__device__ float g_Cc[G_DIM * X_DIM];             // -0.5 * C[g,x]
__device__ float g_mp[G_DIM * NSPLIT * S_DIM];    // partial max
__device__ float g_zp[G_DIM * NSPLIT * S_DIM];    // partial sum-exp

// ---------------------------------------------------------------------------
// prep 1: w = 1/std^2, const[g]
// ---------------------------------------------------------------------------
__global__ void prep_w_kernel(const float* __restrict__ stdp) {
    const int g = blockIdx.x;
    __shared__ float red[256];
    float acc = 0.f;
    for (int f = threadIdx.x; f < F_DIM; f += 256) {
        float sd = stdp[g * F_DIM + f];
        g_w[g * F_DIM + f] = 1.0f / (sd * sd);
        acc += logf(sd);
    }
    red[threadIdx.x] = acc;
    __syncthreads();
    for (int s = 128; s > 0; s >>= 1) {
        if (threadIdx.x < s) red[threadIdx.x] += red[threadIdx.x + s];
        __syncthreads();
    }
    if (threadIdx.x == 0)
        g_const[g] = -0.5f * (float)F_DIM * logf(6.283185307179586f) - red[0];
}

// ---------------------------------------------------------------------------
// prep 2: row terms  out[g*n + r] = -0.5 * sum_f mat[r,f]^2 * w[g,f]
// target = 0 -> g_R (rows = samples), target = 1 -> g_Cc (rows = x)
// ---------------------------------------------------------------------------
__global__ void prep_terms_kernel(const float* __restrict__ mat, int target, int n) {
    const int r = blockIdx.x;
    const float* row = mat + (size_t)r * F_DIM;
    float p0 = 0.f, p1 = 0.f;
    for (int f = threadIdx.x; f < F_DIM; f += 256) {
        float v = row[f];
        float vv = v * v;
        p0 += vv * g_w[f];
        p1 += vv * g_w[F_DIM + f];
    }
    __shared__ float r0[256], r1[256];
    r0[threadIdx.x] = p0; r1[threadIdx.x] = p1;
    __syncthreads();
    for (int s = 128; s > 0; s >>= 1) {
        if (threadIdx.x < s) {
            r0[threadIdx.x] += r0[threadIdx.x + s];
            r1[threadIdx.x] += r1[threadIdx.x + s];
        }
        __syncthreads();
    }
    if (threadIdx.x == 0) {
        float* out = target ? g_Cc : g_R;
        out[r]     = -0.5f * r0[0];
        out[n + r] = -0.5f * r1[0];
    }
}

// ---------------------------------------------------------------------------
// main: fused GEMM (B = s @ (w*x)^T) + online logsumexp over x
// grid: (S/BM, G, NSPLIT), 256 threads, 8x8 per-thread tile
// ---------------------------------------------------------------------------
__global__ __launch_bounds__(256, 2)
void gemm_lse_kernel(const float* __restrict__ Smat, const float* __restrict__ Xmat) {
    __shared__ __align__(16) float ss[2][BK][SLD];
    __shared__ __align__(16) float xs[2][BK][SLD];

    const int tid   = threadIdx.x;
    const int tx    = tid & 15;     // x-col group
    const int ty    = tid >> 4;     // s-row group
    const int g     = blockIdx.y;
    const int split = blockIdx.z;
    const int m0    = blockIdx.x * BM;

    const float cg = g_const[g];
    float Ri[8];
#pragma unroll
    for (int i = 0; i < 8; i++)
        Ri[i] = g_R[g * S_DIM + m0 + ty * 8 + i] + cg;

    float mrow[8], zrow[8];
#pragma unroll
    for (int i = 0; i < 8; i++) { mrow[i] = -INFINITY; zrow[i] = 0.f; }

    const float* wg = g_w + g * F_DIM;

    // load mapping: each thread fills (row, 4 k-values) twice
    const int lrow = tid >> 2;      // 0..63
    const int kc   = (tid & 3) * 4; // 0,4,8,12

    const int NK = F_DIM / BK;      // 192

    for (int xb = 0; xb < XPS / BN; xb++) {
        const int x0 = split * XPS + xb * BN;

        float acc[8][8];
#pragma unroll
        for (int i = 0; i < 8; i++)
#pragma unroll
            for (int j = 0; j < 8; j++) acc[i][j] = 0.f;

        // prologue: tile 0 -> buffer 0
#pragma unroll
        for (int h = 0; h < 2; h++) {
            const int row = lrow + h * 64;
            const float4 v  = *(const float4*)(Smat + (size_t)(m0 + row) * F_DIM + kc);
            ss[0][kc + 0][row] = v.x; ss[0][kc + 1][row] = v.y;
            ss[0][kc + 2][row] = v.z; ss[0][kc + 3][row] = v.w;
            const float4 u  = *(const float4*)(Xmat + (size_t)(x0 + row) * F_DIM + kc);
            const float4 w4 = *(const float4*)(wg + kc);
            xs[0][kc + 0][row] = u.x * w4.x; xs[0][kc + 1][row] = u.y * w4.y;
            xs[0][kc + 2][row] = u.z * w4.z; xs[0][kc + 3][row] = u.w * w4.w;
        }
        __syncthreads();

        for (int kt = 0; kt < NK; kt++) {
            const int cur = kt & 1;
            if (kt + 1 < NK) {
                const int nxt = cur ^ 1;
                const int kb  = (kt + 1) * BK + kc;
#pragma unroll
                for (int h = 0; h < 2; h++) {
                    const int row = lrow + h * 64;
                    const float4 v  = *(const float4*)(Smat + (size_t)(m0 + row) * F_DIM + kb);
                    ss[nxt][kc + 0][row] = v.x; ss[nxt][kc + 1][row] = v.y;
                    ss[nxt][kc + 2][row] = v.z; ss[nxt][kc + 3][row] = v.w;
                    const float4 u  = *(const float4*)(Xmat + (size_t)(x0 + row) * F_DIM + kb);
                    const float4 w4 = *(const float4*)(wg + kb);
                    xs[nxt][kc + 0][row] = u.x * w4.x; xs[nxt][kc + 1][row] = u.y * w4.y;
                    xs[nxt][kc + 2][row] = u.z * w4.z; xs[nxt][kc + 3][row] = u.w * w4.w;
                }
            }
#pragma unroll
            for (int k = 0; k < BK; k++) {
                float a[8], b[8];
                *(float4*)&a[0] = *(const float4*)&ss[cur][k][ty * 8];
                *(float4*)&a[4] = *(const float4*)&ss[cur][k][ty * 8 + 4];
                *(float4*)&b[0] = *(const float4*)&xs[cur][k][tx * 8];
                *(float4*)&b[4] = *(const float4*)&xs[cur][k][tx * 8 + 4];
#pragma unroll
                for (int i = 0; i < 8; i++)
#pragma unroll
                    for (int j = 0; j < 8; j++)
                        acc[i][j] = fmaf(a[i], b[j], acc[i][j]);
            }
            __syncthreads();
        }

        // epilogue: logits = B + (-0.5A + const) + (-0.5C); online LSE per row
        float Ccj[8];
#pragma unroll
        for (int j = 0; j < 8; j++)
            Ccj[j] = g_Cc[g * X_DIM + x0 + tx * 8 + j];

#pragma unroll
        for (int i = 0; i < 8; i++) {
            float l[8];
            float rm = -INFINITY;
#pragma unroll
            for (int j = 0; j < 8; j++) {
                l[j] = acc[i][j] + Ri[i] + Ccj[j];
                rm = fmaxf(rm, l[j]);
            }
            const float nm = fmaxf(mrow[i], rm);
            float sadd = 0.f;
#pragma unroll
            for (int j = 0; j < 8; j++) sadd += __expf(l[j] - nm);
            zrow[i] = zrow[i] * __expf(mrow[i] - nm) + sadd;
            mrow[i] = nm;
        }
    }

    // combine across the 16 lanes (tx) sharing each row group.
    // lanes with the same ty are 16 contiguous lanes of one warp, so
    // xor-shuffles with offsets 1..8 stay inside the group.
#pragma unroll
    for (int i = 0; i < 8; i++) {
        float m = mrow[i], z = zrow[i];
#pragma unroll
        for (int off = 1; off < 16; off <<= 1) {
            const float om = __shfl_xor_sync(0xffffffffu, m, off);
            const float oz = __shfl_xor_sync(0xffffffffu, z, off);
            const float nm = fmaxf(m, om);
            z = z * __expf(m - nm) + oz * __expf(om - nm);
            m = nm;
        }
        if (tx == 0) {
            const int row = m0 + ty * 8 + i;
            g_mp[(g * NSPLIT + split) * S_DIM + row] = m;
            g_zp[(g * NSPLIT + split) * S_DIM + row] = z;
        }
    }
}

// ---------------------------------------------------------------------------
// finalize: combine G*NSPLIT partials per sample
// ---------------------------------------------------------------------------
__global__ void finalize_kernel(float* __restrict__ out) {
    const int s = blockIdx.x * 256 + threadIdx.x;
    if (s >= S_DIM) return;
    float m = -INFINITY;
#pragma unroll
    for (int p = 0; p < G_DIM * NSPLIT; p++)
        m = fmaxf(m, g_mp[p * S_DIM + s]);
    float Z = 0.f;
#pragma unroll
    for (int p = 0; p < G_DIM * NSPLIT; p++)
        Z += g_zp[p * S_DIM + s] * __expf(g_mp[p * S_DIM + s] - m);
    out[s] = m + logf(Z) - logf((float)(X_DIM * G_DIM));
}

// ---------------------------------------------------------------------------
extern "C" void kernel_launch(void* const* d_in, const int* in_sizes, int n_in,
                              void* d_out, int out_size) {
    const float* samples = (const float*)d_in[0];  // [2048, 3072]
    const float* x       = (const float*)d_in[1];  // [2048, 3072]
    const float* stdp    = (const float*)d_in[2];  // [2, 3072]
    float* out = (float*)d_out;                    // [2048]

    prep_w_kernel<<<G_DIM, 256>>>(stdp);
    prep_terms_kernel<<<S_DIM, 256>>>(samples, 0, S_DIM);
    prep_terms_kernel<<<X_DIM, 256>>>(x, 1, X_DIM);

    dim3 grid(S_DIM / BM, G_DIM, NSPLIT);
    gemm_lse_kernel<<<grid, 256>>>(samples, x);

    finalize_kernel<<<(S_DIM + 255) / 256, 256>>>(out);
}

// round 3
// speedup vs baseline: 6.1003x; 6.1003x over previous
#include <cuda_runtime.h>
#include <cuda_bf16.h>
#include <math.h>
#include <stdint.h>

#define S_DIM 2048
#define X_DIM 2048
#define F_DIM 3072
#define G_DIM 2
#define NKC   96              // 3072 / 32
#define NPART 32              // 16 x-blocks * 2 gradations

#define STAGES 4
#define LDE    40                      // bf16 elems per smem row (32 + 8 pad)
#define TILEB  (128 * LDE * 2)         // 10240 B per tile
#define STAGEB (2 * TILEB)             // A + B per stage
#define SM_CC  (STAGES * STAGEB)       // 81920
#define SM_RM  (SM_CC + 512)
#define SM_RZ  (SM_RM + 2048)
#define SMEM_TOTAL (SM_RZ + 2048)      // 86528 B

// ---- scratch (static, no runtime allocation) ----
__device__ float g_w[G_DIM * F_DIM];
__device__ float g_const[G_DIM];
__device__ float g_R[G_DIM * S_DIM];      // -0.5*A
__device__ float g_Cc[G_DIM * X_DIM];     // -0.5*C
__device__ float g_mp[NPART * S_DIM];
__device__ float g_zp[NPART * S_DIM];
__device__ __align__(16) __nv_bfloat16 g_sbuf[(size_t)S_DIM * F_DIM];           // bf16(s)
__device__ __align__(16) __nv_bfloat16 g_xwbuf[(size_t)G_DIM * X_DIM * F_DIM];  // bf16(w*x)

// ---------------------------------------------------------------------------
// PTX helpers (all sm_80-portable; no 'a'-suffix features)
// ---------------------------------------------------------------------------
__device__ __forceinline__ uint32_t smem_u32(const void* p) {
    uint32_t a;
    asm("{ .reg .u64 t; cvta.to.shared.u64 t, %1; cvt.u32.u64 %0, t; }" : "=r"(a) : "l"(p));
    return a;
}
__device__ __forceinline__ void cp16(uint32_t dst, const void* src) {
    asm volatile("cp.async.cg.shared.global [%0], [%1], 16;" :: "r"(dst), "l"(src) : "memory");
}
#define CP_COMMIT() asm volatile("cp.async.commit_group;" ::: "memory")
#define CP_WAIT2()  asm volatile("cp.async.wait_group 2;" ::: "memory")

__device__ __forceinline__ void ldsm_x4(uint32_t& r0, uint32_t& r1, uint32_t& r2, uint32_t& r3,
                                        uint32_t addr) {
    asm volatile("ldmatrix.sync.aligned.m8n8.x4.shared.b16 {%0,%1,%2,%3}, [%4];"
                 : "=r"(r0), "=r"(r1), "=r"(r2), "=r"(r3) : "r"(addr));
}
__device__ __forceinline__ void mma_bf16(float* c,
                                         uint32_t a0, uint32_t a1, uint32_t a2, uint32_t a3,
                                         uint32_t b0, uint32_t b1) {
    asm volatile("mma.sync.aligned.m16n8k16.row.col.f32.bf16.bf16.f32 "
                 "{%0,%1,%2,%3}, {%4,%5,%6,%7}, {%8,%9}, {%0,%1,%2,%3};"
                 : "+f"(c[0]), "+f"(c[1]), "+f"(c[2]), "+f"(c[3])
                 : "r"(a0), "r"(a1), "r"(a2), "r"(a3), "r"(b0), "r"(b1));
}

// ---------------------------------------------------------------------------
// prep 1: w = 1/std^2, const[g]
// ---------------------------------------------------------------------------
__global__ void prep_w_kernel(const float* __restrict__ stdp) {
    const int g = blockIdx.x;
    __shared__ float red[256];
    float acc = 0.f;
    for (int f = threadIdx.x; f < F_DIM; f += 256) {
        float sd = stdp[g * F_DIM + f];
        g_w[g * F_DIM + f] = 1.0f / (sd * sd);
        acc += logf(sd);
    }
    red[threadIdx.x] = acc;
    __syncthreads();
    for (int s = 128; s > 0; s >>= 1) {
        if (threadIdx.x < s) red[threadIdx.x] += red[threadIdx.x + s];
        __syncthreads();
    }
    if (threadIdx.x == 0)
        g_const[g] = -0.5f * (float)F_DIM * logf(6.283185307179586f) - red[0];
}

// ---------------------------------------------------------------------------
// prep 2: row terms -0.5 * sum_f mat[r,f]^2 * w[g,f]   (exact fp32)
// ---------------------------------------------------------------------------
__global__ void prep_terms_kernel(const float* __restrict__ mat, int target, int n) {
    const int r = blockIdx.x;
    const float* row = mat + (size_t)r * F_DIM;
    float p0 = 0.f, p1 = 0.f;
    for (int f = threadIdx.x; f < F_DIM; f += 256) {
        float v = row[f];
        float vv = v * v;
        p0 += vv * g_w[f];
        p1 += vv * g_w[F_DIM + f];
    }
    __shared__ float r0[256], r1[256];
    r0[threadIdx.x] = p0; r1[threadIdx.x] = p1;
    __syncthreads();
    for (int s = 128; s > 0; s >>= 1) {
        if (threadIdx.x < s) {
            r0[threadIdx.x] += r0[threadIdx.x + s];
            r1[threadIdx.x] += r1[threadIdx.x + s];
        }
        __syncthreads();
    }
    if (threadIdx.x == 0) {
        float* out = target ? g_Cc : g_R;
        out[r]     = -0.5f * r0[0];
        out[n + r] = -0.5f * r1[0];
    }
}

// ---------------------------------------------------------------------------
// prep 3: convert s -> bf16  (grid = S_DIM rows, 384 threads x 8 elems)
// ---------------------------------------------------------------------------
__global__ void conv_s_kernel(const float* __restrict__ s) {
    const int row = blockIdx.x;
    const int f0  = threadIdx.x * 8;
    const float4 v0 = *(const float4*)(s + (size_t)row * F_DIM + f0);
    const float4 v1 = *(const float4*)(s + (size_t)row * F_DIM + f0 + 4);
    __nv_bfloat162 p[4];
    p[0] = __float22bfloat162_rn(make_float2(v0.x, v0.y));
    p[1] = __float22bfloat162_rn(make_float2(v0.z, v0.w));
    p[2] = __float22bfloat162_rn(make_float2(v1.x, v1.y));
    p[3] = __float22bfloat162_rn(make_float2(v1.z, v1.w));
    *(uint4*)(g_sbuf + (size_t)row * F_DIM + f0) = *(uint4*)p;
}

// ---------------------------------------------------------------------------
// prep 4: convert w*x -> bf16  (grid = (X_DIM, G), 384 threads x 8 elems)
// ---------------------------------------------------------------------------
__global__ void conv_xw_kernel(const float* __restrict__ x) {
    const int g   = blockIdx.y;
    const int row = blockIdx.x;
    const int f0  = threadIdx.x * 8;
    const float4 v0 = *(const float4*)(x + (size_t)row * F_DIM + f0);
    const float4 v1 = *(const float4*)(x + (size_t)row * F_DIM + f0 + 4);
    const float4 w0 = *(const float4*)(g_w + (size_t)g * F_DIM + f0);
    const float4 w1 = *(const float4*)(g_w + (size_t)g * F_DIM + f0 + 4);
    __nv_bfloat162 p[4];
    p[0] = __float22bfloat162_rn(make_float2(v0.x * w0.x, v0.y * w0.y));
    p[1] = __float22bfloat162_rn(make_float2(v0.z * w0.z, v0.w * w0.w));
    p[2] = __float22bfloat162_rn(make_float2(v1.x * w1.x, v1.y * w1.y));
    p[3] = __float22bfloat162_rn(make_float2(v1.z * w1.z, v1.w * w1.w));
    *(uint4*)(g_xwbuf + ((size_t)g * X_DIM + row) * F_DIM + f0) = *(uint4*)p;
}

// ---------------------------------------------------------------------------
// main: bf16 mma.sync GEMM (128x128 tile) + fused online LSE over x
// grid (16 sblk, 16 xblk, 2 g), 256 threads (8 warps, 2x4)
// ---------------------------------------------------------------------------
__device__ __forceinline__ void issue_chunk(uint32_t sbase, int st, int kc,
                                            const char* Ag, const char* Bg, int tid) {
    const int r  = tid >> 2;
    const int ks = tid & 3;
    const uint32_t aT = sbase + (uint32_t)st * STAGEB;
    const uint32_t bT = aT + TILEB;
    const size_t   go = (size_t)r * (F_DIM * 2) + (size_t)kc * 64 + (size_t)ks * 16;
    const size_t   g2 = (size_t)64 * (F_DIM * 2);
    const uint32_t so = (uint32_t)r * (LDE * 2) + (uint32_t)ks * 16;
    cp16(aT + so,                 Ag + go);
    cp16(aT + so + 64 * LDE * 2,  Ag + go + g2);
    cp16(bT + so,                 Bg + go);
    cp16(bT + so + 64 * LDE * 2,  Bg + go + g2);
    CP_COMMIT();
}

__global__ __launch_bounds__(256, 2)
void gemm_lse_mma_kernel() {
    extern __shared__ __align__(1024) char smem[];
    const uint32_t sbase = smem_u32(smem);

    const int tid  = threadIdx.x;
    const int wid  = tid >> 5;
    const int lane = tid & 31;
    const int wr   = wid >> 2;   // 0..1
    const int wc   = wid & 3;    // 0..3
    const int tg   = lane >> 2;  // 0..7
    const int tt   = lane & 3;   // 0..3

    const int g  = blockIdx.z;
    const int m0 = blockIdx.x * 128;
    const int x0 = blockIdx.y * 128;

    const char* Ag = (const char*)(g_sbuf  + (size_t)m0 * F_DIM);
    const char* Bg = (const char*)(g_xwbuf + ((size_t)g * X_DIM + x0) * F_DIM);

    float* sCc = (float*)(smem + SM_CC);
    float* sRm = (float*)(smem + SM_RM);
    float* sRz = (float*)(smem + SM_RZ);
    if (tid < 128) sCc[tid] = g_Cc[g * X_DIM + x0 + tid];

    float acc[4][4][4];
#pragma unroll
    for (int mt = 0; mt < 4; mt++)
#pragma unroll
        for (int nt = 0; nt < 4; nt++)
#pragma unroll
            for (int j = 0; j < 4; j++) acc[mt][nt][j] = 0.f;

    // prologue: prefetch STAGES-1 chunks
    for (int i = 0; i < STAGES - 1; i++) issue_chunk(sbase, i, i, Ag, Bg, tid);

    // per-thread ldmatrix offsets (bytes within tile)
    const uint32_t aRowOff = (uint32_t)(wr * 64 + (lane & 15)) * (LDE * 2)
                           + (uint32_t)((lane >> 4) * 8) * 2;
    const int bgrp = lane >> 3;
    const uint32_t bRowOff = (uint32_t)(wc * 32 + ((bgrp >> 1) * 8) + (lane & 7)) * (LDE * 2)
                           + (uint32_t)((bgrp & 1) * 8) * 2;

    for (int kc = 0; kc < NKC; kc++) {
        const int st = kc & (STAGES - 1);
        CP_WAIT2();
        __syncthreads();
        const uint32_t aT = sbase + (uint32_t)st * STAGEB;
        const uint32_t bT = aT + TILEB;

#pragma unroll
        for (int ks = 0; ks < 2; ks++) {
            uint32_t a[4][4];
#pragma unroll
            for (int mt = 0; mt < 4; mt++)
                ldsm_x4(a[mt][0], a[mt][1], a[mt][2], a[mt][3],
                        aT + aRowOff + (uint32_t)(mt * 16) * (LDE * 2) + (uint32_t)(ks * 32));
            uint32_t b[4][2];
#pragma unroll
            for (int np = 0; np < 2; np++)
                ldsm_x4(b[2 * np][0], b[2 * np][1], b[2 * np + 1][0], b[2 * np + 1][1],
                        bT + bRowOff + (uint32_t)(np * 16) * (LDE * 2) + (uint32_t)(ks * 32));
#pragma unroll
            for (int mt = 0; mt < 4; mt++)
#pragma unroll
                for (int nt = 0; nt < 4; nt++)
                    mma_bf16(acc[mt][nt], a[mt][0], a[mt][1], a[mt][2], a[mt][3],
                             b[nt][0], b[nt][1]);
        }
        if (kc + STAGES - 1 < NKC)
            issue_chunk(sbase, (kc + STAGES - 1) & (STAGES - 1), kc + STAGES - 1, Ag, Bg, tid);
    }
    __syncthreads();

    // ---------------- fused LSE epilogue ----------------
    const float cg = g_const[g];
#pragma unroll
    for (int mt = 0; mt < 4; mt++) {
#pragma unroll
        for (int half = 0; half < 2; half++) {
            const int r = wr * 64 + mt * 16 + tg + half * 8;
            const float Ri = g_R[g * S_DIM + m0 + r] + cg;
            float l[8];
            float m = -INFINITY;
#pragma unroll
            for (int nt = 0; nt < 4; nt++) {
                const float c0 = sCc[wc * 32 + nt * 8 + tt * 2];
                const float c1 = sCc[wc * 32 + nt * 8 + tt * 2 + 1];
                l[2 * nt + 0] = acc[mt][nt][half * 2 + 0] + Ri + c0;
                l[2 * nt + 1] = acc[mt][nt][half * 2 + 1] + Ri + c1;
                m = fmaxf(m, fmaxf(l[2 * nt], l[2 * nt + 1]));
            }
            float z = 0.f;
#pragma unroll
            for (int j = 0; j < 8; j++) z += __expf(l[j] - m);
            // reduce across the 4 lanes (tt) sharing this row
#pragma unroll
            for (int off = 1; off < 4; off <<= 1) {
                const float om = __shfl_xor_sync(0xffffffffu, m, off);
                const float oz = __shfl_xor_sync(0xffffffffu, z, off);
                const float nm = fmaxf(m, om);
                z = z * __expf(m - nm) + oz * __expf(om - nm);
                m = nm;
            }
            if (tt == 0) { sRm[r * 4 + wc] = m; sRz[r * 4 + wc] = z; }
        }
    }
    __syncthreads();

    if (tid < 128) {
        float m = -INFINITY;
#pragma unroll
        for (int i = 0; i < 4; i++) m = fmaxf(m, sRm[tid * 4 + i]);
        float z = 0.f;
#pragma unroll
        for (int i = 0; i < 4; i++) z += sRz[tid * 4 + i] * __expf(sRm[tid * 4 + i] - m);
        const int p = g * 16 + blockIdx.y;
        g_mp[p * S_DIM + m0 + tid] = m;
        g_zp[p * S_DIM + m0 + tid] = z;
    }
}

// ---------------------------------------------------------------------------
// finalize: combine NPART partials per sample
// ---------------------------------------------------------------------------
__global__ void finalize_kernel(float* __restrict__ out) {
    const int s = blockIdx.x * 256 + threadIdx.x;
    if (s >= S_DIM) return;
    float m = -INFINITY;
#pragma unroll
    for (int p = 0; p < NPART; p++)
        m = fmaxf(m, g_mp[p * S_DIM + s]);
    float Z = 0.f;
#pragma unroll
    for (int p = 0; p < NPART; p++)
        Z += g_zp[p * S_DIM + s] * __expf(g_mp[p * S_DIM + s] - m);
    out[s] = m + logf(Z) - logf((float)(X_DIM * G_DIM));
}

// ---------------------------------------------------------------------------
extern "C" void kernel_launch(void* const* d_in, const int* in_sizes, int n_in,
                              void* d_out, int out_size) {
    const float* samples = (const float*)d_in[0];  // [2048, 3072]
    const float* x       = (const float*)d_in[1];  // [2048, 3072]
    const float* stdp    = (const float*)d_in[2];  // [2, 3072]
    float* out = (float*)d_out;                    // [2048]

    cudaFuncSetAttribute(gemm_lse_mma_kernel,
                         cudaFuncAttributeMaxDynamicSharedMemorySize, SMEM_TOTAL);

    prep_w_kernel<<<G_DIM, 256>>>(stdp);
    prep_terms_kernel<<<S_DIM, 256>>>(samples, 0, S_DIM);
    prep_terms_kernel<<<X_DIM, 256>>>(x, 1, X_DIM);
    conv_s_kernel<<<S_DIM, 384>>>(samples);
    {
        dim3 gx(X_DIM, G_DIM);
        conv_xw_kernel<<<gx, 384>>>(x);
    }

    dim3 grid(S_DIM / 128, X_DIM / 128, G_DIM);
    gemm_lse_mma_kernel<<<grid, 256, SMEM_TOTAL>>>();

    finalize_kernel<<<(S_DIM + 255) / 256, 256>>>(out);
}

// round 4
// speedup vs baseline: 6.5284x; 1.0702x over previous
#include <cuda_runtime.h>
#include <cuda_bf16.h>
#include <math.h>
#include <stdint.h>

#define S_DIM 2048
#define X_DIM 2048
#define F_DIM 3072
#define G_DIM 2
#define NKC   96              // 3072 / 32
#define NPART 32              // 16 x-blocks * 2 gradations

#define STAGES 4
#define LDE    40                      // bf16 elems per smem row (32 + 8 pad)
#define TILEB  (128 * LDE * 2)         // 10240 B per tile
#define STAGEB (2 * TILEB)             // A + B per stage
#define SM_CC  (STAGES * STAGEB)       // 81920
#define SM_RM  (SM_CC + 512)
#define SM_RZ  (SM_RM + 2048)
#define SMEM_TOTAL (SM_RZ + 2048)      // 86528 B

// ---- scratch (static, no runtime allocation) ----
__device__ float g_w[G_DIM * F_DIM];
__device__ float g_const[G_DIM];
__device__ float g_R[G_DIM * S_DIM];      // -0.5*A
__device__ float g_Cc[G_DIM * X_DIM];     // -0.5*C
__device__ float g_mp[NPART * S_DIM];
__device__ float g_zp[NPART * S_DIM];
__device__ __align__(16) __nv_bfloat16 g_sbuf[(size_t)S_DIM * F_DIM];           // bf16(s)
__device__ __align__(16) __nv_bfloat16 g_xwbuf[(size_t)G_DIM * X_DIM * F_DIM];  // bf16(w*x)

// ---------------------------------------------------------------------------
// PTX helpers (all sm_80-portable; no 'a'-suffix features)
// ---------------------------------------------------------------------------
__device__ __forceinline__ uint32_t smem_u32(const void* p) {
    uint32_t a;
    asm("{ .reg .u64 t; cvta.to.shared.u64 t, %1; cvt.u32.u64 %0, t; }" : "=r"(a) : "l"(p));
    return a;
}
__device__ __forceinline__ void cp16(uint32_t dst, const void* src) {
    asm volatile("cp.async.cg.shared.global [%0], [%1], 16;" :: "r"(dst), "l"(src) : "memory");
}
#define CP_COMMIT() asm volatile("cp.async.commit_group;" ::: "memory")
#define CP_WAIT2()  asm volatile("cp.async.wait_group 2;" ::: "memory")

__device__ __forceinline__ void ldsm_x4(uint32_t& r0, uint32_t& r1, uint32_t& r2, uint32_t& r3,
                                        uint32_t addr) {
    asm volatile("ldmatrix.sync.aligned.m8n8.x4.shared.b16 {%0,%1,%2,%3}, [%4];"
                 : "=r"(r0), "=r"(r1), "=r"(r2), "=r"(r3) : "r"(addr));
}
__device__ __forceinline__ void mma_bf16(float* c,
                                         uint32_t a0, uint32_t a1, uint32_t a2, uint32_t a3,
                                         uint32_t b0, uint32_t b1) {
    asm volatile("mma.sync.aligned.m16n8k16.row.col.f32.bf16.bf16.f32 "
                 "{%0,%1,%2,%3}, {%4,%5,%6,%7}, {%8,%9}, {%0,%1,%2,%3};"
                 : "+f"(c[0]), "+f"(c[1]), "+f"(c[2]), "+f"(c[3])
                 : "r"(a0), "r"(a1), "r"(a2), "r"(a3), "r"(b0), "r"(b1));
}

// ---------------------------------------------------------------------------
// prep 1: w = 1/std^2, const[g]
// ---------------------------------------------------------------------------
__global__ void prep_w_kernel(const float* __restrict__ stdp) {
    const int g = blockIdx.x;
    __shared__ float red[256];
    float acc = 0.f;
    for (int f = threadIdx.x; f < F_DIM; f += 256) {
        float sd = stdp[g * F_DIM + f];
        g_w[g * F_DIM + f] = 1.0f / (sd * sd);
        acc += logf(sd);
    }
    red[threadIdx.x] = acc;
    __syncthreads();
    for (int s = 128; s > 0; s >>= 1) {
        if (threadIdx.x < s) red[threadIdx.x] += red[threadIdx.x + s];
        __syncthreads();
    }
    if (threadIdx.x == 0)
        g_const[g] = -0.5f * (float)F_DIM * logf(6.283185307179586f) - red[0];
}

// ---------------------------------------------------------------------------
// fused prep: one block per row (384 threads, 8 floats/thread).
//   blocks [0, 2048):   samples row -> bf16(g_sbuf) + g_R[g][row]
//   blocks [2048, 4096): x row      -> bf16(w*x) for g=0,1 + g_Cc[g][row]
// ---------------------------------------------------------------------------
__global__ __launch_bounds__(384)
void fused_prep_kernel(const float* __restrict__ samples, const float* __restrict__ x) {
    const int bid  = blockIdx.x;
    const int tid  = threadIdx.x;
    const int lane = tid & 31;
    const int wrp  = tid >> 5;          // 0..11
    const int f0   = tid * 8;
    __shared__ float red0[12], red1[12];

    const int is_x = (bid >= S_DIM);
    const int row  = is_x ? bid - S_DIM : bid;
    const float* src = (is_x ? x : samples) + (size_t)row * F_DIM + f0;

    const float4 v0 = *(const float4*)(src);
    const float4 v1 = *(const float4*)(src + 4);
    const float4 w00 = *(const float4*)(g_w + f0);
    const float4 w01 = *(const float4*)(g_w + f0 + 4);
    const float4 w10 = *(const float4*)(g_w + F_DIM + f0);
    const float4 w11 = *(const float4*)(g_w + F_DIM + f0 + 4);

    // weighted square sums for both gradations
    float p0 = v0.x*v0.x*w00.x + v0.y*v0.y*w00.y + v0.z*v0.z*w00.z + v0.w*v0.w*w00.w
             + v1.x*v1.x*w01.x + v1.y*v1.y*w01.y + v1.z*v1.z*w01.z + v1.w*v1.w*w01.w;
    float p1 = v0.x*v0.x*w10.x + v0.y*v0.y*w10.y + v0.z*v0.z*w10.z + v0.w*v0.w*w10.w
             + v1.x*v1.x*w11.x + v1.y*v1.y*w11.y + v1.z*v1.z*w11.z + v1.w*v1.w*w11.w;

    if (!is_x) {
        __nv_bfloat162 p[4];
        p[0] = __float22bfloat162_rn(make_float2(v0.x, v0.y));
        p[1] = __float22bfloat162_rn(make_float2(v0.z, v0.w));
        p[2] = __float22bfloat162_rn(make_float2(v1.x, v1.y));
        p[3] = __float22bfloat162_rn(make_float2(v1.z, v1.w));
        *(uint4*)(g_sbuf + (size_t)row * F_DIM + f0) = *(uint4*)p;
    } else {
        __nv_bfloat162 p[4];
        p[0] = __float22bfloat162_rn(make_float2(v0.x * w00.x, v0.y * w00.y));
        p[1] = __float22bfloat162_rn(make_float2(v0.z * w00.z, v0.w * w00.w));
        p[2] = __float22bfloat162_rn(make_float2(v1.x * w01.x, v1.y * w01.y));
        p[3] = __float22bfloat162_rn(make_float2(v1.z * w01.z, v1.w * w01.w));
        *(uint4*)(g_xwbuf + (size_t)row * F_DIM + f0) = *(uint4*)p;
        p[0] = __float22bfloat162_rn(make_float2(v0.x * w10.x, v0.y * w10.y));
        p[1] = __float22bfloat162_rn(make_float2(v0.z * w10.z, v0.w * w10.w));
        p[2] = __float22bfloat162_rn(make_float2(v1.x * w11.x, v1.y * w11.y));
        p[3] = __float22bfloat162_rn(make_float2(v1.z * w11.z, v1.w * w11.w));
        *(uint4*)(g_xwbuf + ((size_t)X_DIM + row) * F_DIM + f0) = *(uint4*)p;
    }

    // reduce p0/p1 across 384 threads
#pragma unroll
    for (int off = 16; off > 0; off >>= 1) {
        p0 += __shfl_xor_sync(0xffffffffu, p0, off);
        p1 += __shfl_xor_sync(0xffffffffu, p1, off);
    }
    if (lane == 0) { red0[wrp] = p0; red1[wrp] = p1; }
    __syncthreads();
    if (tid == 0) {
        float s0 = 0.f, s1 = 0.f;
#pragma unroll
        for (int i = 0; i < 12; i++) { s0 += red0[i]; s1 += red1[i]; }
        float* out = is_x ? g_Cc : g_R;
        const int n = is_x ? X_DIM : S_DIM;
        out[row]     = -0.5f * s0;
        out[n + row] = -0.5f * s1;
    }
}

// ---------------------------------------------------------------------------
// main: bf16 mma.sync GEMM (128x128 tile) + fused online LSE over x
// grid (16 sblk, 16 xblk, 2 g), 256 threads (8 warps, 2x4)
// ---------------------------------------------------------------------------
__device__ __forceinline__ void issue_chunk(uint32_t sbase, int st, int kc,
                                            const char* Ag, const char* Bg, int tid) {
    const int r  = tid >> 2;
    const int ks = tid & 3;
    const uint32_t aT = sbase + (uint32_t)st * STAGEB;
    const uint32_t bT = aT + TILEB;
    const size_t   go = (size_t)r * (F_DIM * 2) + (size_t)kc * 64 + (size_t)ks * 16;
    const size_t   g2 = (size_t)64 * (F_DIM * 2);
    const uint32_t so = (uint32_t)r * (LDE * 2) + (uint32_t)ks * 16;
    cp16(aT + so,                 Ag + go);
    cp16(aT + so + 64 * LDE * 2,  Ag + go + g2);
    cp16(bT + so,                 Bg + go);
    cp16(bT + so + 64 * LDE * 2,  Bg + go + g2);
    CP_COMMIT();
}

__global__ __launch_bounds__(256, 2)
void gemm_lse_mma_kernel() {
    extern __shared__ __align__(1024) char smem[];
    const uint32_t sbase = smem_u32(smem);

    const int tid  = threadIdx.x;
    const int wid  = tid >> 5;
    const int lane = tid & 31;
    const int wr   = wid >> 2;   // 0..1
    const int wc   = wid & 3;    // 0..3
    const int tg   = lane >> 2;  // 0..7
    const int tt   = lane & 3;   // 0..3

    const int g  = blockIdx.z;
    const int m0 = blockIdx.x * 128;
    const int x0 = blockIdx.y * 128;

    const char* Ag = (const char*)(g_sbuf  + (size_t)m0 * F_DIM);
    const char* Bg = (const char*)(g_xwbuf + ((size_t)g * X_DIM + x0) * F_DIM);

    float* sCc = (float*)(smem + SM_CC);
    float* sRm = (float*)(smem + SM_RM);
    float* sRz = (float*)(smem + SM_RZ);
    if (tid < 128) sCc[tid] = g_Cc[g * X_DIM + x0 + tid];

    float acc[4][4][4];
#pragma unroll
    for (int mt = 0; mt < 4; mt++)
#pragma unroll
        for (int nt = 0; nt < 4; nt++)
#pragma unroll
            for (int j = 0; j < 4; j++) acc[mt][nt][j] = 0.f;

    // prologue: prefetch STAGES-1 chunks
    for (int i = 0; i < STAGES - 1; i++) issue_chunk(sbase, i, i, Ag, Bg, tid);

    // per-thread ldmatrix offsets (bytes within tile)
    const uint32_t aRowOff = (uint32_t)(wr * 64 + (lane & 15)) * (LDE * 2)
                           + (uint32_t)((lane >> 4) * 8) * 2;
    const int bgrp = lane >> 3;
    const uint32_t bRowOff = (uint32_t)(wc * 32 + ((bgrp >> 1) * 8) + (lane & 7)) * (LDE * 2)
                           + (uint32_t)((bgrp & 1) * 8) * 2;

    for (int kc = 0; kc < NKC; kc++) {
        const int st = kc & (STAGES - 1);
        CP_WAIT2();
        __syncthreads();

        // issue the NEXT chunk's loads first so they overlap this chunk's MMAs.
        // Target stage (kc+STAGES-1)&3 == (kc-1)&3 was fully consumed before
        // the barrier above, so the write is safe.
        if (kc + STAGES - 1 < NKC)
            issue_chunk(sbase, (kc + STAGES - 1) & (STAGES - 1), kc + STAGES - 1, Ag, Bg, tid);

        const uint32_t aT = sbase + (uint32_t)st * STAGEB;
        const uint32_t bT = aT + TILEB;

#pragma unroll
        for (int ks = 0; ks < 2; ks++) {
            uint32_t a[4][4];
#pragma unroll
            for (int mt = 0; mt < 4; mt++)
                ldsm_x4(a[mt][0], a[mt][1], a[mt][2], a[mt][3],
                        aT + aRowOff + (uint32_t)(mt * 16) * (LDE * 2) + (uint32_t)(ks * 32));
            uint32_t b[4][2];
#pragma unroll
            for (int np = 0; np < 2; np++)
                ldsm_x4(b[2 * np][0], b[2 * np][1], b[2 * np + 1][0], b[2 * np + 1][1],
                        bT + bRowOff + (uint32_t)(np * 16) * (LDE * 2) + (uint32_t)(ks * 32));
#pragma unroll
            for (int mt = 0; mt < 4; mt++)
#pragma unroll
                for (int nt = 0; nt < 4; nt++)
                    mma_bf16(acc[mt][nt], a[mt][0], a[mt][1], a[mt][2], a[mt][3],
                             b[nt][0], b[nt][1]);
        }
    }
    __syncthreads();

    // ---------------- fused LSE epilogue ----------------
    const float cg = g_const[g];
#pragma unroll
    for (int mt = 0; mt < 4; mt++) {
#pragma unroll
        for (int half = 0; half < 2; half++) {
            const int r = wr * 64 + mt * 16 + tg + half * 8;
            const float Ri = g_R[g * S_DIM + m0 + r] + cg;
            float l[8];
            float m = -INFINITY;
#pragma unroll
            for (int nt = 0; nt < 4; nt++) {
                const float c0 = sCc[wc * 32 + nt * 8 + tt * 2];
                const float c1 = sCc[wc * 32 + nt * 8 + tt * 2 + 1];
                l[2 * nt + 0] = acc[mt][nt][half * 2 + 0] + Ri + c0;
                l[2 * nt + 1] = acc[mt][nt][half * 2 + 1] + Ri + c1;
                m = fmaxf(m, fmaxf(l[2 * nt], l[2 * nt + 1]));
            }
            float z = 0.f;
#pragma unroll
            for (int j = 0; j < 8; j++) z += __expf(l[j] - m);
            // reduce across the 4 lanes (tt) sharing this row
#pragma unroll
            for (int off = 1; off < 4; off <<= 1) {
                const float om = __shfl_xor_sync(0xffffffffu, m, off);
                const float oz = __shfl_xor_sync(0xffffffffu, z, off);
                const float nm = fmaxf(m, om);
                z = z * __expf(m - nm) + oz * __expf(om - nm);
                m = nm;
            }
            if (tt == 0) { sRm[r * 4 + wc] = m; sRz[r * 4 + wc] = z; }
        }
    }
    __syncthreads();

    if (tid < 128) {
        float m = -INFINITY;
#pragma unroll
        for (int i = 0; i < 4; i++) m = fmaxf(m, sRm[tid * 4 + i]);
        float z = 0.f;
#pragma unroll
        for (int i = 0; i < 4; i++) z += sRz[tid * 4 + i] * __expf(sRm[tid * 4 + i] - m);
        const int p = g * 16 + blockIdx.y;
        g_mp[p * S_DIM + m0 + tid] = m;
        g_zp[p * S_DIM + m0 + tid] = z;
    }
}

// ---------------------------------------------------------------------------
// finalize: combine NPART partials per sample
// ---------------------------------------------------------------------------
__global__ void finalize_kernel(float* __restrict__ out) {
    const int s = blockIdx.x * 256 + threadIdx.x;
    if (s >= S_DIM) return;
    float m = -INFINITY;
#pragma unroll
    for (int p = 0; p < NPART; p++)
        m = fmaxf(m, g_mp[p * S_DIM + s]);
    float Z = 0.f;
#pragma unroll
    for (int p = 0; p < NPART; p++)
        Z += g_zp[p * S_DIM + s] * __expf(g_mp[p * S_DIM + s] - m);
    out[s] = m + logf(Z) - logf((float)(X_DIM * G_DIM));
}

// ---------------------------------------------------------------------------
extern "C" void kernel_launch(void* const* d_in, const int* in_sizes, int n_in,
                              void* d_out, int out_size) {
    const float* samples = (const float*)d_in[0];  // [2048, 3072]
    const float* x       = (const float*)d_in[1];  // [2048, 3072]
    const float* stdp    = (const float*)d_in[2];  // [2, 3072]
    float* out = (float*)d_out;                    // [2048]

    cudaFuncSetAttribute(gemm_lse_mma_kernel,
                         cudaFuncAttributeMaxDynamicSharedMemorySize, SMEM_TOTAL);

    prep_w_kernel<<<G_DIM, 256>>>(stdp);
    fused_prep_kernel<<<S_DIM + X_DIM, 384>>>(samples, x);

    dim3 grid(S_DIM / 128, X_DIM / 128, G_DIM);
    gemm_lse_mma_kernel<<<grid, 256, SMEM_TOTAL>>>();

    finalize_kernel<<<(S_DIM + 255) / 256, 256>>>(out);
}

// round 5
// speedup vs baseline: 7.0139x; 1.0744x over previous
#include <cuda_runtime.h>
#include <cuda_bf16.h>
#include <math.h>
#include <stdint.h>

#define S_DIM 2048
#define X_DIM 2048
#define F_DIM 3072
#define G_DIM 2
#define NKC   48              // 3072 / 64
#define NPART 32              // 16 x-blocks * 2 gradations

#define STAGES 3
#define LDE    72                      // bf16 elems per smem row (64 + 8 pad)
#define TILEB  (128 * LDE * 2)         // 18432 B per tile
#define STAGEB (2 * TILEB)             // A + B per stage = 36864
#define SM_CC  (STAGES * STAGEB)       // 110592
#define SM_RM  (SM_CC + 512)
#define SM_RZ  (SM_RM + 2048)
#define SMEM_TOTAL (SM_RZ + 2048)      // 115200 B

// ---- scratch (static, no runtime allocation) ----
__device__ float g_w[G_DIM * F_DIM];
__device__ float g_const[G_DIM];
__device__ float g_R[G_DIM * S_DIM];      // -0.5*A
__device__ float g_Cc[G_DIM * X_DIM];     // -0.5*C
__device__ float g_mp[NPART * S_DIM];
__device__ float g_zp[NPART * S_DIM];
__device__ __align__(16) __nv_bfloat16 g_sbuf[(size_t)S_DIM * F_DIM];           // bf16(s)
__device__ __align__(16) __nv_bfloat16 g_xwbuf[(size_t)G_DIM * X_DIM * F_DIM];  // bf16(w*x)

// ---------------------------------------------------------------------------
// PTX helpers (all sm_80-portable; no 'a'-suffix features)
// ---------------------------------------------------------------------------
__device__ __forceinline__ uint32_t smem_u32(const void* p) {
    uint32_t a;
    asm("{ .reg .u64 t; cvta.to.shared.u64 t, %1; cvt.u32.u64 %0, t; }" : "=r"(a) : "l"(p));
    return a;
}
__device__ __forceinline__ void cp16(uint32_t dst, const void* src) {
    asm volatile("cp.async.cg.shared.global [%0], [%1], 16;" :: "r"(dst), "l"(src) : "memory");
}
#define CP_COMMIT() asm volatile("cp.async.commit_group;" ::: "memory")
#define CP_WAIT1()  asm volatile("cp.async.wait_group 1;" ::: "memory")

__device__ __forceinline__ void ldsm_x4(uint32_t& r0, uint32_t& r1, uint32_t& r2, uint32_t& r3,
                                        uint32_t addr) {
    asm volatile("ldmatrix.sync.aligned.m8n8.x4.shared.b16 {%0,%1,%2,%3}, [%4];"
                 : "=r"(r0), "=r"(r1), "=r"(r2), "=r"(r3) : "r"(addr));
}
__device__ __forceinline__ void mma_bf16(float* c,
                                         uint32_t a0, uint32_t a1, uint32_t a2, uint32_t a3,
                                         uint32_t b0, uint32_t b1) {
    asm volatile("mma.sync.aligned.m16n8k16.row.col.f32.bf16.bf16.f32 "
                 "{%0,%1,%2,%3}, {%4,%5,%6,%7}, {%8,%9}, {%0,%1,%2,%3};"
                 : "+f"(c[0]), "+f"(c[1]), "+f"(c[2]), "+f"(c[3])
                 : "r"(a0), "r"(a1), "r"(a2), "r"(a3), "r"(b0), "r"(b1));
}

// ---------------------------------------------------------------------------
// prep 1: w = 1/std^2, const[g]
// ---------------------------------------------------------------------------
__global__ void prep_w_kernel(const float* __restrict__ stdp) {
    const int g = blockIdx.x;
    __shared__ float red[256];
    float acc = 0.f;
    for (int f = threadIdx.x; f < F_DIM; f += 256) {
        float sd = stdp[g * F_DIM + f];
        g_w[g * F_DIM + f] = 1.0f / (sd * sd);
        acc += logf(sd);
    }
    red[threadIdx.x] = acc;
    __syncthreads();
    for (int s = 128; s > 0; s >>= 1) {
        if (threadIdx.x < s) red[threadIdx.x] += red[threadIdx.x + s];
        __syncthreads();
    }
    if (threadIdx.x == 0)
        g_const[g] = -0.5f * (float)F_DIM * logf(6.283185307179586f) - red[0];
}

// ---------------------------------------------------------------------------
// prep 2a: samples row -> bf16(g_sbuf) + g_R[g][row]   (one block/row)
// ---------------------------------------------------------------------------
__global__ __launch_bounds__(384)
void prep_s_kernel(const float* __restrict__ samples) {
    const int row  = blockIdx.x;
    const int tid  = threadIdx.x;
    const int lane = tid & 31;
    const int wrp  = tid >> 5;
    const int f0   = tid * 8;
    __shared__ float red0[12], red1[12];

    const float* src = samples + (size_t)row * F_DIM + f0;
    const float4 v0 = *(const float4*)(src);
    const float4 v1 = *(const float4*)(src + 4);
    const float4 w00 = *(const float4*)(g_w + f0);
    const float4 w01 = *(const float4*)(g_w + f0 + 4);
    const float4 w10 = *(const float4*)(g_w + F_DIM + f0);
    const float4 w11 = *(const float4*)(g_w + F_DIM + f0 + 4);

    float p0 = v0.x*v0.x*w00.x + v0.y*v0.y*w00.y + v0.z*v0.z*w00.z + v0.w*v0.w*w00.w
             + v1.x*v1.x*w01.x + v1.y*v1.y*w01.y + v1.z*v1.z*w01.z + v1.w*v1.w*w01.w;
    float p1 = v0.x*v0.x*w10.x + v0.y*v0.y*w10.y + v0.z*v0.z*w10.z + v0.w*v0.w*w10.w
             + v1.x*v1.x*w11.x + v1.y*v1.y*w11.y + v1.z*v1.z*w11.z + v1.w*v1.w*w11.w;

    __nv_bfloat162 p[4];
    p[0] = __float22bfloat162_rn(make_float2(v0.x, v0.y));
    p[1] = __float22bfloat162_rn(make_float2(v0.z, v0.w));
    p[2] = __float22bfloat162_rn(make_float2(v1.x, v1.y));
    p[3] = __float22bfloat162_rn(make_float2(v1.z, v1.w));
    *(uint4*)(g_sbuf + (size_t)row * F_DIM + f0) = *(uint4*)p;

#pragma unroll
    for (int off = 16; off > 0; off >>= 1) {
        p0 += __shfl_xor_sync(0xffffffffu, p0, off);
        p1 += __shfl_xor_sync(0xffffffffu, p1, off);
    }
    if (lane == 0) { red0[wrp] = p0; red1[wrp] = p1; }
    __syncthreads();
    if (tid == 0) {
        float s0 = 0.f, s1 = 0.f;
#pragma unroll
        for (int i = 0; i < 12; i++) { s0 += red0[i]; s1 += red1[i]; }
        g_R[row]         = -0.5f * s0;
        g_R[S_DIM + row] = -0.5f * s1;
    }
}

// ---------------------------------------------------------------------------
// prep 2b: x row -> bf16(w*x) for g=0,1 + g_Cc[g][row]   (one block/row)
// ---------------------------------------------------------------------------
__global__ __launch_bounds__(384)
void prep_x_kernel(const float* __restrict__ x) {
    const int row  = blockIdx.x;
    const int tid  = threadIdx.x;
    const int lane = tid & 31;
    const int wrp  = tid >> 5;
    const int f0   = tid * 8;
    __shared__ float red0[12], red1[12];

    const float* src = x + (size_t)row * F_DIM + f0;
    const float4 v0 = *(const float4*)(src);
    const float4 v1 = *(const float4*)(src + 4);
    const float4 w00 = *(const float4*)(g_w + f0);
    const float4 w01 = *(const float4*)(g_w + f0 + 4);
    const float4 w10 = *(const float4*)(g_w + F_DIM + f0);
    const float4 w11 = *(const float4*)(g_w + F_DIM + f0 + 4);

    float p0 = v0.x*v0.x*w00.x + v0.y*v0.y*w00.y + v0.z*v0.z*w00.z + v0.w*v0.w*w00.w
             + v1.x*v1.x*w01.x + v1.y*v1.y*w01.y + v1.z*v1.z*w01.z + v1.w*v1.w*w01.w;
    float p1 = v0.x*v0.x*w10.x + v0.y*v0.y*w10.y + v0.z*v0.z*w10.z + v0.w*v0.w*w10.w
             + v1.x*v1.x*w11.x + v1.y*v1.y*w11.y + v1.z*v1.z*w11.z + v1.w*v1.w*w11.w;

    __nv_bfloat162 p[4];
    p[0] = __float22bfloat162_rn(make_float2(v0.x * w00.x, v0.y * w00.y));
    p[1] = __float22bfloat162_rn(make_float2(v0.z * w00.z, v0.w * w00.w));
    p[2] = __float22bfloat162_rn(make_float2(v1.x * w01.x, v1.y * w01.y));
    p[3] = __float22bfloat162_rn(make_float2(v1.z * w01.z, v1.w * w01.w));
    *(uint4*)(g_xwbuf + (size_t)row * F_DIM + f0) = *(uint4*)p;
    p[0] = __float22bfloat162_rn(make_float2(v0.x * w10.x, v0.y * w10.y));
    p[1] = __float22bfloat162_rn(make_float2(v0.z * w10.z, v0.w * w10.w));
    p[2] = __float22bfloat162_rn(make_float2(v1.x * w11.x, v1.y * w11.y));
    p[3] = __float22bfloat162_rn(make_float2(v1.z * w11.z, v1.w * w11.w));
    *(uint4*)(g_xwbuf + ((size_t)X_DIM + row) * F_DIM + f0) = *(uint4*)p;

#pragma unroll
    for (int off = 16; off > 0; off >>= 1) {
        p0 += __shfl_xor_sync(0xffffffffu, p0, off);
        p1 += __shfl_xor_sync(0xffffffffu, p1, off);
    }
    if (lane == 0) { red0[wrp] = p0; red1[wrp] = p1; }
    __syncthreads();
    if (tid == 0) {
        float s0 = 0.f, s1 = 0.f;
#pragma unroll
        for (int i = 0; i < 12; i++) { s0 += red0[i]; s1 += red1[i]; }
        g_Cc[row]         = -0.5f * s0;
        g_Cc[X_DIM + row] = -0.5f * s1;
    }
}

// ---------------------------------------------------------------------------
// main: bf16 mma.sync GEMM (128x128 tile, BK=64) + fused online LSE over x
// grid (16 sblk, 16 xblk, 2 g), 256 threads (8 warps, 2x4)
// ---------------------------------------------------------------------------
__device__ __forceinline__ void issue_chunk(uint32_t sbase, int st, int kc,
                                            const char* Ag, const char* Bg, int tid) {
    const int r = tid >> 3;              // 0..31
    const int c = (tid & 7) * 16;        // byte col within 128B row
    const uint32_t aT = sbase + (uint32_t)st * STAGEB;
    const uint32_t bT = aT + TILEB;
    const size_t gstep = (size_t)32 * (F_DIM * 2);
    const size_t go = (size_t)r * (F_DIM * 2) + (size_t)kc * 128 + (size_t)c;
    const uint32_t so = (uint32_t)r * (LDE * 2) + (uint32_t)c;
#pragma unroll
    for (int i = 0; i < 4; i++) {
        cp16(aT + so + (uint32_t)i * 32 * (LDE * 2), Ag + go + (size_t)i * gstep);
        cp16(bT + so + (uint32_t)i * 32 * (LDE * 2), Bg + go + (size_t)i * gstep);
    }
    CP_COMMIT();
}

__global__ __launch_bounds__(256, 2)
void gemm_lse_mma_kernel() {
    extern __shared__ __align__(1024) char smem[];
    const uint32_t sbase = smem_u32(smem);

    const int tid  = threadIdx.x;
    const int wid  = tid >> 5;
    const int lane = tid & 31;
    const int wr   = wid >> 2;   // 0..1
    const int wc   = wid & 3;    // 0..3
    const int tg   = lane >> 2;  // 0..7
    const int tt   = lane & 3;   // 0..3

    const int g  = blockIdx.z;
    const int m0 = blockIdx.x * 128;
    const int x0 = blockIdx.y * 128;

    const char* Ag = (const char*)(g_sbuf  + (size_t)m0 * F_DIM);
    const char* Bg = (const char*)(g_xwbuf + ((size_t)g * X_DIM + x0) * F_DIM);

    float* sCc = (float*)(smem + SM_CC);
    float* sRm = (float*)(smem + SM_RM);
    float* sRz = (float*)(smem + SM_RZ);
    if (tid < 128) sCc[tid] = g_Cc[g * X_DIM + x0 + tid];

    float acc[4][4][4];
#pragma unroll
    for (int mt = 0; mt < 4; mt++)
#pragma unroll
        for (int nt = 0; nt < 4; nt++)
#pragma unroll
            for (int j = 0; j < 4; j++) acc[mt][nt][j] = 0.f;

    // prologue: prefetch 2 chunks
    issue_chunk(sbase, 0, 0, Ag, Bg, tid);
    issue_chunk(sbase, 1, 1, Ag, Bg, tid);

    // per-thread ldmatrix offsets (bytes within tile)
    const uint32_t aRowOff = (uint32_t)(wr * 64 + (lane & 15)) * (LDE * 2)
                           + (uint32_t)((lane >> 4) * 8) * 2;
    const int bgrp = lane >> 3;
    const uint32_t bRowOff = (uint32_t)(wc * 32 + ((bgrp >> 1) * 8) + (lane & 7)) * (LDE * 2)
                           + (uint32_t)((bgrp & 1) * 8) * 2;

    int st = 0, stn = 2;   // current stage, issue-target stage
#pragma unroll 1
    for (int kc = 0; kc < NKC; kc++) {
        CP_WAIT1();
        __syncthreads();

        // issue chunk kc+2 into stage stn == (kc-1)%3, consumed before this barrier
        if (kc + 2 < NKC)
            issue_chunk(sbase, stn, kc + 2, Ag, Bg, tid);

        const uint32_t aT = sbase + (uint32_t)st * STAGEB;
        const uint32_t bT = aT + TILEB;

#pragma unroll
        for (int ks = 0; ks < 4; ks++) {
            uint32_t a[4][4];
#pragma unroll
            for (int mt = 0; mt < 4; mt++)
                ldsm_x4(a[mt][0], a[mt][1], a[mt][2], a[mt][3],
                        aT + aRowOff + (uint32_t)(mt * 16) * (LDE * 2) + (uint32_t)(ks * 32));
            uint32_t b[4][2];
#pragma unroll
            for (int np = 0; np < 2; np++)
                ldsm_x4(b[2 * np][0], b[2 * np][1], b[2 * np + 1][0], b[2 * np + 1][1],
                        bT + bRowOff + (uint32_t)(np * 16) * (LDE * 2) + (uint32_t)(ks * 32));
#pragma unroll
            for (int mt = 0; mt < 4; mt++)
#pragma unroll
                for (int nt = 0; nt < 4; nt++)
                    mma_bf16(acc[mt][nt], a[mt][0], a[mt][1], a[mt][2], a[mt][3],
                             b[nt][0], b[nt][1]);
        }
        st  = (st  == 2) ? 0 : st  + 1;
        stn = (stn == 2) ? 0 : stn + 1;
    }
    __syncthreads();

    // ---------------- fused LSE epilogue ----------------
    const float cg = g_const[g];
#pragma unroll
    for (int mt = 0; mt < 4; mt++) {
#pragma unroll
        for (int half = 0; half < 2; half++) {
            const int r = wr * 64 + mt * 16 + tg + half * 8;
            const float Ri = g_R[g * S_DIM + m0 + r] + cg;
            float l[8];
            float m = -INFINITY;
#pragma unroll
            for (int nt = 0; nt < 4; nt++) {
                const float c0 = sCc[wc * 32 + nt * 8 + tt * 2];
                const float c1 = sCc[wc * 32 + nt * 8 + tt * 2 + 1];
                l[2 * nt + 0] = acc[mt][nt][half * 2 + 0] + Ri + c0;
                l[2 * nt + 1] = acc[mt][nt][half * 2 + 1] + Ri + c1;
                m = fmaxf(m, fmaxf(l[2 * nt], l[2 * nt + 1]));
            }
            float z = 0.f;
#pragma unroll
            for (int j = 0; j < 8; j++) z += __expf(l[j] - m);
#pragma unroll
            for (int off = 1; off < 4; off <<= 1) {
                const float om = __shfl_xor_sync(0xffffffffu, m, off);
                const float oz = __shfl_xor_sync(0xffffffffu, z, off);
                const float nm = fmaxf(m, om);
                z = z * __expf(m - nm) + oz * __expf(om - nm);
                m = nm;
            }
            if (tt == 0) { sRm[r * 4 + wc] = m; sRz[r * 4 + wc] = z; }
        }
    }
    __syncthreads();

    if (tid < 128) {
        float m = -INFINITY;
#pragma unroll
        for (int i = 0; i < 4; i++) m = fmaxf(m, sRm[tid * 4 + i]);
        float z = 0.f;
#pragma unroll
        for (int i = 0; i < 4; i++) z += sRz[tid * 4 + i] * __expf(sRm[tid * 4 + i] - m);
        const int p = g * 16 + blockIdx.y;
        g_mp[p * S_DIM + m0 + tid] = m;
        g_zp[p * S_DIM + m0 + tid] = z;
    }
}

// ---------------------------------------------------------------------------
// finalize: combine NPART partials per sample
// ---------------------------------------------------------------------------
__global__ void finalize_kernel(float* __restrict__ out) {
    const int s = blockIdx.x * 256 + threadIdx.x;
    if (s >= S_DIM) return;
    float m = -INFINITY;
#pragma unroll
    for (int p = 0; p < NPART; p++)
        m = fmaxf(m, g_mp[p * S_DIM + s]);
    float Z = 0.f;
#pragma unroll
    for (int p = 0; p < NPART; p++)
        Z += g_zp[p * S_DIM + s] * __expf(g_mp[p * S_DIM + s] - m);
    out[s] = m + logf(Z) - logf((float)(X_DIM * G_DIM));
}

// ---------------------------------------------------------------------------
extern "C" void kernel_launch(void* const* d_in, const int* in_sizes, int n_in,
                              void* d_out, int out_size) {
    const float* samples = (const float*)d_in[0];  // [2048, 3072]
    const float* x       = (const float*)d_in[1];  // [2048, 3072]
    const float* stdp    = (const float*)d_in[2];  // [2, 3072]
    float* out = (float*)d_out;                    // [2048]

    cudaFuncSetAttribute(gemm_lse_mma_kernel,
                         cudaFuncAttributeMaxDynamicSharedMemorySize, SMEM_TOTAL);

    prep_w_kernel<<<G_DIM, 256>>>(stdp);        // launch 1
    prep_s_kernel<<<S_DIM, 384>>>(samples);     // launch 2
    prep_x_kernel<<<X_DIM, 384>>>(x);           // launch 3

    dim3 grid(S_DIM / 128, X_DIM / 128, G_DIM);
    gemm_lse_mma_kernel<<<grid, 256, SMEM_TOTAL>>>();   // launch 4 (ncu target)

    finalize_kernel<<<(S_DIM + 255) / 256, 256>>>(out); // launch 5
}

// round 6
// speedup vs baseline: 7.0294x; 1.0022x over previous
#include <cuda_runtime.h>
#include <cuda_bf16.h>
#include <math.h>
#include <stdint.h>

#define S_DIM 2048
#define X_DIM 2048
#define F_DIM 3072
#define G_DIM 2
#define NKC   48              // 3072 / 64
#define NPART 32              // 16 x-blocks * 2 gradations
#define NTILES 512            // 16 * 16 * 2

#define LDE    72                      // bf16 elems per smem row (64 + 8 pad)
#define LDE2   (LDE * 2)               // bytes per row (144)
#define TILEB  (128 * LDE2)            // 18432 B per tile
#define STAGEB (2 * TILEB)             // A + B per stage = 36864
#define SMEM_TOTAL (3 * STAGEB)        // 110592 B  (epilogue arrays overlap stage 0)

// ---- scratch (static, no runtime allocation) ----
__device__ float g_w[G_DIM * F_DIM];
__device__ float g_const[G_DIM];
__device__ float g_R[G_DIM * S_DIM];      // -0.5*A
__device__ float g_Cc[G_DIM * X_DIM];     // -0.5*C
__device__ float g_mp[NPART * S_DIM];
__device__ float g_zp[NPART * S_DIM];
__device__ unsigned g_ticket = 0;         // reset by winner each launch
__device__ __align__(16) __nv_bfloat16 g_sbuf[(size_t)S_DIM * F_DIM];           // bf16(s)
__device__ __align__(16) __nv_bfloat16 g_xwbuf[(size_t)G_DIM * X_DIM * F_DIM];  // bf16(w*x)

// ---------------------------------------------------------------------------
// PTX helpers (all sm_80-portable; no 'a'-suffix features)
// ---------------------------------------------------------------------------
__device__ __forceinline__ uint32_t smem_u32(const void* p) {
    uint32_t a;
    asm("{ .reg .u64 t; cvta.to.shared.u64 t, %1; cvt.u32.u64 %0, t; }" : "=r"(a) : "l"(p));
    return a;
}
__device__ __forceinline__ void cp16(uint32_t dst, const void* src) {
    asm volatile("cp.async.cg.shared.global [%0], [%1], 16;" :: "r"(dst), "l"(src) : "memory");
}
#define CP_COMMIT() asm volatile("cp.async.commit_group;" ::: "memory")
#define CP_WAIT1()  asm volatile("cp.async.wait_group 1;" ::: "memory")

__device__ __forceinline__ void ldsm_x4(uint32_t& r0, uint32_t& r1, uint32_t& r2, uint32_t& r3,
                                        uint32_t addr) {
    asm volatile("ldmatrix.sync.aligned.m8n8.x4.shared.b16 {%0,%1,%2,%3}, [%4];"
                 : "=r"(r0), "=r"(r1), "=r"(r2), "=r"(r3) : "r"(addr));
}
__device__ __forceinline__ void mma_bf16(float* c,
                                         const uint32_t* a,
                                         uint32_t b0, uint32_t b1) {
    asm volatile("mma.sync.aligned.m16n8k16.row.col.f32.bf16.bf16.f32 "
                 "{%0,%1,%2,%3}, {%4,%5,%6,%7}, {%8,%9}, {%0,%1,%2,%3};"
                 : "+f"(c[0]), "+f"(c[1]), "+f"(c[2]), "+f"(c[3])
                 : "r"(a[0]), "r"(a[1]), "r"(a[2]), "r"(a[3]), "r"(b0), "r"(b1));
}

// ---------------------------------------------------------------------------
// prep 1: w = 1/std^2, const[g]
// ---------------------------------------------------------------------------
__global__ void prep_w_kernel(const float* __restrict__ stdp) {
    const int g = blockIdx.x;
    __shared__ float red[256];
    float acc = 0.f;
    for (int f = threadIdx.x; f < F_DIM; f += 256) {
        float sd = stdp[g * F_DIM + f];
        g_w[g * F_DIM + f] = 1.0f / (sd * sd);
        acc += logf(sd);
    }
    red[threadIdx.x] = acc;
    __syncthreads();
    for (int s = 128; s > 0; s >>= 1) {
        if (threadIdx.x < s) red[threadIdx.x] += red[threadIdx.x + s];
        __syncthreads();
    }
    if (threadIdx.x == 0)
        g_const[g] = -0.5f * (float)F_DIM * logf(6.283185307179586f) - red[0];
}

// ---------------------------------------------------------------------------
// prep 2a: samples row -> bf16(g_sbuf) + g_R[g][row]   (one block/row)
// ---------------------------------------------------------------------------
__global__ __launch_bounds__(384)
void prep_s_kernel(const float* __restrict__ samples) {
    const int row  = blockIdx.x;
    const int tid  = threadIdx.x;
    const int lane = tid & 31;
    const int wrp  = tid >> 5;
    const int f0   = tid * 8;
    __shared__ float red0[12], red1[12];

    const float* src = samples + (size_t)row * F_DIM + f0;
    const float4 v0 = *(const float4*)(src);
    const float4 v1 = *(const float4*)(src + 4);
    const float4 w00 = *(const float4*)(g_w + f0);
    const float4 w01 = *(const float4*)(g_w + f0 + 4);
    const float4 w10 = *(const float4*)(g_w + F_DIM + f0);
    const float4 w11 = *(const float4*)(g_w + F_DIM + f0 + 4);

    float p0 = v0.x*v0.x*w00.x + v0.y*v0.y*w00.y + v0.z*v0.z*w00.z + v0.w*v0.w*w00.w
             + v1.x*v1.x*w01.x + v1.y*v1.y*w01.y + v1.z*v1.z*w01.z + v1.w*v1.w*w01.w;
    float p1 = v0.x*v0.x*w10.x + v0.y*v0.y*w10.y + v0.z*v0.z*w10.z + v0.w*v0.w*w10.w
             + v1.x*v1.x*w11.x + v1.y*v1.y*w11.y + v1.z*v1.z*w11.z + v1.w*v1.w*w11.w;

    __nv_bfloat162 p[4];
    p[0] = __float22bfloat162_rn(make_float2(v0.x, v0.y));
    p[1] = __float22bfloat162_rn(make_float2(v0.z, v0.w));
    p[2] = __float22bfloat162_rn(make_float2(v1.x, v1.y));
    p[3] = __float22bfloat162_rn(make_float2(v1.z, v1.w));
    *(uint4*)(g_sbuf + (size_t)row * F_DIM + f0) = *(uint4*)p;

#pragma unroll
    for (int off = 16; off > 0; off >>= 1) {
        p0 += __shfl_xor_sync(0xffffffffu, p0, off);
        p1 += __shfl_xor_sync(0xffffffffu, p1, off);
    }
    if (lane == 0) { red0[wrp] = p0; red1[wrp] = p1; }
    __syncthreads();
    if (tid == 0) {
        float s0 = 0.f, s1 = 0.f;
#pragma unroll
        for (int i = 0; i < 12; i++) { s0 += red0[i]; s1 += red1[i]; }
        g_R[row]         = -0.5f * s0;
        g_R[S_DIM + row] = -0.5f * s1;
    }
}

// ---------------------------------------------------------------------------
// prep 2b: x row -> bf16(w*x) for g=0,1 + g_Cc[g][row]   (one block/row)
// ---------------------------------------------------------------------------
__global__ __launch_bounds__(384)
void prep_x_kernel(const float* __restrict__ x) {
    const int row  = blockIdx.x;
    const int tid  = threadIdx.x;
    const int lane = tid & 31;
    const int wrp  = tid >> 5;
    const int f0   = tid * 8;
    __shared__ float red0[12], red1[12];

    const float* src = x + (size_t)row * F_DIM + f0;
    const float4 v0 = *(const float4*)(src);
    const float4 v1 = *(const float4*)(src + 4);
    const float4 w00 = *(const float4*)(g_w + f0);
    const float4 w01 = *(const float4*)(g_w + f0 + 4);
    const float4 w10 = *(const float4*)(g_w + F_DIM + f0);
    const float4 w11 = *(const float4*)(g_w + F_DIM + f0 + 4);

    float p0 = v0.x*v0.x*w00.x + v0.y*v0.y*w00.y + v0.z*v0.z*w00.z + v0.w*v0.w*w00.w
             + v1.x*v1.x*w01.x + v1.y*v1.y*w01.y + v1.z*v1.z*w01.z + v1.w*v1.w*w01.w;
    float p1 = v0.x*v0.x*w10.x + v0.y*v0.y*w10.y + v0.z*v0.z*w10.z + v0.w*v0.w*w10.w
             + v1.x*v1.x*w11.x + v1.y*v1.y*w11.y + v1.z*v1.z*w11.z + v1.w*v1.w*w11.w;

    __nv_bfloat162 p[4];
    p[0] = __float22bfloat162_rn(make_float2(v0.x * w00.x, v0.y * w00.y));
    p[1] = __float22bfloat162_rn(make_float2(v0.z * w00.z, v0.w * w00.w));
    p[2] = __float22bfloat162_rn(make_float2(v1.x * w01.x, v1.y * w01.y));
    p[3] = __float22bfloat162_rn(make_float2(v1.z * w01.z, v1.w * w01.w));
    *(uint4*)(g_xwbuf + (size_t)row * F_DIM + f0) = *(uint4*)p;
    p[0] = __float22bfloat162_rn(make_float2(v0.x * w10.x, v0.y * w10.y));
    p[1] = __float22bfloat162_rn(make_float2(v0.z * w10.z, v0.w * w10.w));
    p[2] = __float22bfloat162_rn(make_float2(v1.x * w11.x, v1.y * w11.y));
    p[3] = __float22bfloat162_rn(make_float2(v1.z * w11.z, v1.w * w11.w));
    *(uint4*)(g_xwbuf + ((size_t)X_DIM + row) * F_DIM + f0) = *(uint4*)p;

#pragma unroll
    for (int off = 16; off > 0; off >>= 1) {
        p0 += __shfl_xor_sync(0xffffffffu, p0, off);
        p1 += __shfl_xor_sync(0xffffffffu, p1, off);
    }
    if (lane == 0) { red0[wrp] = p0; red1[wrp] = p1; }
    __syncthreads();
    if (tid == 0) {
        float s0 = 0.f, s1 = 0.f;
#pragma unroll
        for (int i = 0; i < 12; i++) { s0 += red0[i]; s1 += red1[i]; }
        g_Cc[row]         = -0.5f * s0;
        g_Cc[X_DIM + row] = -0.5f * s1;
    }
}

// ---------------------------------------------------------------------------
// main: bf16 mma.sync GEMM (128x128 tile, BK=64) + fused online LSE over x
// grid (16 sblk, 16 xblk, 2 g), 256 threads (8 warps, 2x4)
// last 8 CTAs (atomic ticket) also run the global finalize in the tail wave.
// ---------------------------------------------------------------------------
__device__ __forceinline__ void issue_chunk(uint32_t sbase, int st, int kc,
                                            const char* Ag, const char* Bg, int tid) {
    const int r = tid >> 3;              // 0..31
    const int c = (tid & 7) * 16;        // byte col within 128B row
    const uint32_t aT = sbase + (uint32_t)st * STAGEB;
    const uint32_t bT = aT + TILEB;
    const size_t gstep = (size_t)32 * (F_DIM * 2);
    const size_t go = (size_t)r * (F_DIM * 2) + (size_t)kc * 128 + (size_t)c;
    const uint32_t so = (uint32_t)r * LDE2 + (uint32_t)c;
#pragma unroll
    for (int i = 0; i < 4; i++) {
        cp16(aT + so + (uint32_t)i * 32 * LDE2, Ag + go + (size_t)i * gstep);
        cp16(bT + so + (uint32_t)i * 32 * LDE2, Bg + go + (size_t)i * gstep);
    }
    CP_COMMIT();
}

__global__ __launch_bounds__(256, 2)
void gemm_lse_mma_kernel(float* __restrict__ out) {
    extern __shared__ __align__(1024) char smem[];
    const uint32_t sbase = smem_u32(smem);

    const int tid  = threadIdx.x;
    const int wid  = tid >> 5;
    const int lane = tid & 31;
    const int wr   = wid >> 2;   // 0..1
    const int wc   = wid & 3;    // 0..3
    const int tg   = lane >> 2;  // 0..7
    const int tt   = lane & 3;   // 0..3

    const int g  = blockIdx.z;
    const int m0 = blockIdx.x * 128;
    const int x0 = blockIdx.y * 128;

    const char* Ag = (const char*)(g_sbuf  + (size_t)m0 * F_DIM);
    const char* Bg = (const char*)(g_xwbuf + ((size_t)g * X_DIM + x0) * F_DIM);

    float acc[4][4][4];
#pragma unroll
    for (int mt = 0; mt < 4; mt++)
#pragma unroll
        for (int nt = 0; nt < 4; nt++)
#pragma unroll
            for (int j = 0; j < 4; j++) acc[mt][nt][j] = 0.f;

    // prologue: prefetch 2 chunks
    issue_chunk(sbase, 0, 0, Ag, Bg, tid);
    issue_chunk(sbase, 1, 1, Ag, Bg, tid);

    // per-thread ldmatrix offsets (bytes within tile)
    const uint32_t aRowOff = (uint32_t)(wr * 64 + (lane & 15)) * LDE2
                           + (uint32_t)((lane >> 4) * 8) * 2;
    const int bgrp = lane >> 3;
    const uint32_t bRowOff = (uint32_t)(wc * 32 + ((bgrp >> 1) * 8) + (lane & 7)) * LDE2
                           + (uint32_t)((bgrp & 1) * 8) * 2;

    int st = 0, stn = 2;   // current stage, issue-target stage
#pragma unroll 1
    for (int kc = 0; kc < NKC; kc++) {
        CP_WAIT1();
        __syncthreads();

        if (kc + 2 < NKC)
            issue_chunk(sbase, stn, kc + 2, Ag, Bg, tid);

        const uint32_t aT = sbase + (uint32_t)st * STAGEB;
        const uint32_t bT = aT + TILEB;

#pragma unroll
        for (int ks = 0; ks < 4; ks++) {
            const uint32_t kso = (uint32_t)(ks * 32);
            // B fragments first (both n-halves)
            uint32_t b[8];
            ldsm_x4(b[0], b[1], b[2], b[3], bT + bRowOff + kso);
            ldsm_x4(b[4], b[5], b[6], b[7], bT + bRowOff + 16u * LDE2 + kso);
            // A fragments JIT-rotated through two buffers
            uint32_t a0[4], a1[4];
            ldsm_x4(a0[0], a0[1], a0[2], a0[3], aT + aRowOff + kso);
            ldsm_x4(a1[0], a1[1], a1[2], a1[3], aT + aRowOff + 16u * LDE2 + kso);
            mma_bf16(acc[0][0], a0, b[0], b[1]);
            mma_bf16(acc[0][1], a0, b[2], b[3]);
            mma_bf16(acc[0][2], a0, b[4], b[5]);
            mma_bf16(acc[0][3], a0, b[6], b[7]);
            ldsm_x4(a0[0], a0[1], a0[2], a0[3], aT + aRowOff + 32u * LDE2 + kso);
            mma_bf16(acc[1][0], a1, b[0], b[1]);
            mma_bf16(acc[1][1], a1, b[2], b[3]);
            mma_bf16(acc[1][2], a1, b[4], b[5]);
            mma_bf16(acc[1][3], a1, b[6], b[7]);
            ldsm_x4(a1[0], a1[1], a1[2], a1[3], aT + aRowOff + 48u * LDE2 + kso);
            mma_bf16(acc[2][0], a0, b[0], b[1]);
            mma_bf16(acc[2][1], a0, b[2], b[3]);
            mma_bf16(acc[2][2], a0, b[4], b[5]);
            mma_bf16(acc[2][3], a0, b[6], b[7]);
            mma_bf16(acc[3][0], a1, b[0], b[1]);
            mma_bf16(acc[3][1], a1, b[2], b[3]);
            mma_bf16(acc[3][2], a1, b[4], b[5]);
            mma_bf16(acc[3][3], a1, b[6], b[7]);
        }
        st  = (st  == 2) ? 0 : st  + 1;
        stn = (stn == 2) ? 0 : stn + 1;
    }
    __syncthreads();   // stages dead; epilogue arrays may now overlap them

    float* sRm = (float*)(smem);           // 128 rows * 4 warps
    float* sRz = (float*)(smem + 2048);

    // ---------------- fused LSE epilogue ----------------
    const float cg = g_const[g];
    float Ccj[8];
#pragma unroll
    for (int nt = 0; nt < 4; nt++) {
        Ccj[2 * nt + 0] = g_Cc[g * X_DIM + x0 + wc * 32 + nt * 8 + tt * 2];
        Ccj[2 * nt + 1] = g_Cc[g * X_DIM + x0 + wc * 32 + nt * 8 + tt * 2 + 1];
    }
#pragma unroll
    for (int mt = 0; mt < 4; mt++) {
#pragma unroll
        for (int half = 0; half < 2; half++) {
            const int r = wr * 64 + mt * 16 + tg + half * 8;
            const float Ri = g_R[g * S_DIM + m0 + r] + cg;
            float l[8];
            float m = -INFINITY;
#pragma unroll
            for (int j = 0; j < 8; j++) {
                l[j] = acc[mt][j >> 1][half * 2 + (j & 1)] + Ri + Ccj[j];
                m = fmaxf(m, l[j]);
            }
            float z = 0.f;
#pragma unroll
            for (int j = 0; j < 8; j++) z += __expf(l[j] - m);
#pragma unroll
            for (int off = 1; off < 4; off <<= 1) {
                const float om = __shfl_xor_sync(0xffffffffu, m, off);
                const float oz = __shfl_xor_sync(0xffffffffu, z, off);
                const float nm = fmaxf(m, om);
                z = z * __expf(m - nm) + oz * __expf(om - nm);
                m = nm;
            }
            if (tt == 0) { sRm[r * 4 + wc] = m; sRz[r * 4 + wc] = z; }
        }
    }
    __syncthreads();

    if (tid < 128) {
        float m = -INFINITY;
#pragma unroll
        for (int i = 0; i < 4; i++) m = fmaxf(m, sRm[tid * 4 + i]);
        float z = 0.f;
#pragma unroll
        for (int i = 0; i < 4; i++) z += sRz[tid * 4 + i] * __expf(sRm[tid * 4 + i] - m);
        const int p = g * 16 + blockIdx.y;
        g_mp[p * S_DIM + m0 + tid] = m;
        g_zp[p * S_DIM + m0 + tid] = z;
    }

    // ---------------- inline finalize by the last 8 CTAs ----------------
    __shared__ unsigned s_ticket;
    __threadfence();
    __syncthreads();
    if (tid == 0) s_ticket = atomicAdd(&g_ticket, 1u);
    __syncthreads();
    const unsigned tk = s_ticket;
    if (tk >= NTILES - 8) {
        __threadfence();                       // all partials visible
        const int seg = (int)(tk - (NTILES - 8));   // 0..7
        const int s0 = seg * 256;
        const int s  = s0 + tid;
        float m = -INFINITY;
#pragma unroll
        for (int p = 0; p < NPART; p++)
            m = fmaxf(m, g_mp[p * S_DIM + s]);
        float Z = 0.f;
#pragma unroll
        for (int p = 0; p < NPART; p++)
            Z += g_zp[p * S_DIM + s] * __expf(g_mp[p * S_DIM + s] - m);
        out[s] = m + logf(Z) - logf((float)(X_DIM * G_DIM));
        if (tk == NTILES - 1 && tid == 0) g_ticket = 0;   // reset for next replay
    }
}

// ---------------------------------------------------------------------------
extern "C" void kernel_launch(void* const* d_in, const int* in_sizes, int n_in,
                              void* d_out, int out_size) {
    const float* samples = (const float*)d_in[0];  // [2048, 3072]
    const float* x       = (const float*)d_in[1];  // [2048, 3072]
    const float* stdp    = (const float*)d_in[2];  // [2, 3072]
    float* out = (float*)d_out;                    // [2048]

    cudaFuncSetAttribute(gemm_lse_mma_kernel,
                         cudaFuncAttributeMaxDynamicSharedMemorySize, SMEM_TOTAL);

    prep_w_kernel<<<G_DIM, 256>>>(stdp);        // launch 1
    prep_s_kernel<<<S_DIM, 384>>>(samples);     // launch 2
    prep_x_kernel<<<X_DIM, 384>>>(x);           // launch 3

    dim3 grid(S_DIM / 128, X_DIM / 128, G_DIM);
    gemm_lse_mma_kernel<<<grid, 256, SMEM_TOTAL>>>(out);   // launch 4 (ncu target)
}